// round 6
// baseline (speedup 1.0000x reference)
#include <cuda_runtime.h>
#include <math.h>
#include <float.h>
#include <stdint.h>

#define Bb  8
#define Cc  256
#define HH  160
#define WW  160
#define HDs 40
#define WDs 40
#define NT  1600            // tokens per batch
#define MT  (Bb*NT)         // 12800 total tokens
#define NTP 1664            // padded token count (13*128)
#define ATW 1664            // padded attention width
#define NBLK 13

// tf32 smem geometry (words): [r][k] stride 36, [k][r] stride 136
#define TA_SZ 4608          // max(128*36, 32*136)
#define SMEM_T ((4*TA_SZ) * 4)          // 73728 B: As0,As1,Bs0,Bs1

// ---------------- static scratch ----------------
__device__ float g_ds_rgb[Bb*Cc*NTP];                 // [B,C,Np] tf32, pad cols 0
__device__ float g_ds_ir [Bb*Cc*NTP];
__device__ float g_tok[6][MT*Cc + 64*Cc];             // [B*N, C] tf32 (+zero tail)
__device__ float g_attn0[((size_t)MT + 64)*ATW];      // exp(scores) tf32, pads 0
__device__ float g_attn1[((size_t)MT + 64)*ATW];
__device__ float g_psum[2*Bb*NT*NBLK];
__device__ float g_rowinv[2*Bb*NT];
__device__ float g_zcat[MT*2*Cc];                     // [B*N, 2C] tf32-rounded
__device__ float g_pre[3][MT*Cc];
__device__ float g_fused[Bb*Cc*NT];
__device__ float g_w[655360];                         // tf32-rounded weights

__device__ __forceinline__ unsigned f2tf(float x) {
    unsigned r; asm("cvt.rna.tf32.f32 %0, %1;" : "=r"(r) : "f"(x)); return r;
}
__device__ __forceinline__ float f2tff(float x) { return __uint_as_float(f2tf(x)); }

__device__ __forceinline__ void cpa16(const void* smem_dst, const void* gsrc) {
    uint32_t s = (uint32_t)__cvta_generic_to_shared(smem_dst);
    asm volatile("cp.async.cg.shared.global [%0], [%1], 16;" :: "r"(s), "l"(gsrc));
}

// ============ tf32 core: 128(M) x 128(N) block, 256 thr, warp tile 32x64 ============
// AT: 0 = A [m][k] (lda), 1 = A [k][m] (lda)
// BT: 0 = B [n][k] (ldb), 1 = B [k][n] (ldb)
template<int AT, int BT>
__device__ __forceinline__ void gemm128_tf32(
    const float* __restrict__ A, int lda,
    const float* __restrict__ B, int ldb,
    int K, float acc[2][8][4], float* sm)
{
    float* As0 = sm;            float* As1 = sm + TA_SZ;
    float* Bs0 = sm + 2*TA_SZ;  float* Bs1 = sm + 3*TA_SZ;
    const int tid = threadIdx.x, lane = tid & 31, warp = tid >> 5;
    const int wm = (warp >> 1) * 32, wn = (warp & 1) * 64;
    const int g = lane >> 2, tg = lane & 3;

    auto issue = [&](int k0, int bufi) {
        float* as = bufi ? As1 : As0;
        float* bs = bufi ? Bs1 : Bs0;
#pragma unroll
        for (int i = 0; i < 4; i++) {
            int idx = tid + i * 256;
            if (AT == 0) { int m = idx >> 3, kg = (idx & 7) * 4;
                cpa16(as + m * 36 + kg, A + (size_t)m * lda + k0 + kg);
            } else {       int k = idx >> 5, mg = (idx & 31) * 4;
                cpa16(as + k * 136 + mg, A + (size_t)(k0 + k) * lda + mg);
            }
            if (BT == 0) { int n = idx >> 3, kg = (idx & 7) * 4;
                cpa16(bs + n * 36 + kg, B + (size_t)n * ldb + k0 + kg);
            } else {       int k = idx >> 5, ng = (idx & 31) * 4;
                cpa16(bs + k * 136 + ng, B + (size_t)(k0 + k) * ldb + ng);
            }
        }
        asm volatile("cp.async.commit_group;");
    };

    issue(0, 0);
    int buf = 0;
    for (int k0 = 0; k0 < K; k0 += 32) {
        asm volatile("cp.async.wait_group 0;");
        __syncthreads();
        if (k0 + 32 < K) issue(k0 + 32, buf ^ 1);
        const float* as = buf ? As1 : As0;
        const float* bs = buf ? Bs1 : Bs0;
#pragma unroll
        for (int s = 0; s < 4; s++) {
            const int kk = s * 8;
            unsigned a[2][4], b[8][2];
#pragma unroll
            for (int mi = 0; mi < 2; mi++) {
                int r = wm + mi * 16 + g;
                if (AT == 0) {
                    a[mi][0] = __float_as_uint(as[r * 36 + kk + tg]);
                    a[mi][1] = __float_as_uint(as[(r + 8) * 36 + kk + tg]);
                    a[mi][2] = __float_as_uint(as[r * 36 + kk + tg + 4]);
                    a[mi][3] = __float_as_uint(as[(r + 8) * 36 + kk + tg + 4]);
                } else {
                    a[mi][0] = __float_as_uint(as[(kk + tg) * 136 + r]);
                    a[mi][1] = __float_as_uint(as[(kk + tg) * 136 + r + 8]);
                    a[mi][2] = __float_as_uint(as[(kk + tg + 4) * 136 + r]);
                    a[mi][3] = __float_as_uint(as[(kk + tg + 4) * 136 + r + 8]);
                }
            }
#pragma unroll
            for (int ni = 0; ni < 8; ni++) {
                int n = wn + ni * 8 + g;
                if (BT == 0) {
                    b[ni][0] = __float_as_uint(bs[n * 36 + kk + tg]);
                    b[ni][1] = __float_as_uint(bs[n * 36 + kk + tg + 4]);
                } else {
                    b[ni][0] = __float_as_uint(bs[(kk + tg) * 136 + n]);
                    b[ni][1] = __float_as_uint(bs[(kk + tg + 4) * 136 + n]);
                }
            }
#pragma unroll
            for (int mi = 0; mi < 2; mi++)
#pragma unroll
                for (int ni = 0; ni < 8; ni++) {
                    asm volatile(
                        "mma.sync.aligned.m16n8k8.row.col.f32.tf32.tf32.f32 "
                        "{%0,%1,%2,%3}, {%4,%5,%6,%7}, {%8,%9}, {%0,%1,%2,%3};"
                        : "+f"(acc[mi][ni][0]), "+f"(acc[mi][ni][1]),
                          "+f"(acc[mi][ni][2]), "+f"(acc[mi][ni][3])
                        : "r"(a[mi][0]), "r"(a[mi][1]), "r"(a[mi][2]), "r"(a[mi][3]),
                          "r"(b[ni][0]), "r"(b[ni][1]));
                }
        }
        buf ^= 1;
    }
}

// ---------------- weight prep ----------------
__global__ void wprep_kernel(
    const float* w0, const float* w1, const float* w2, const float* w3,
    const float* w4, const float* w5, const float* w6, const float* w7,
    const float* w8)
{
    int seg = blockIdx.y;
    int idx = blockIdx.x * 256 + threadIdx.x;
    int size = (seg == 8) ? 131072 : 65536;
    if (idx >= size) return;
    const float* src;
    switch (seg) {
        case 0: src = w0; break; case 1: src = w1; break; case 2: src = w2; break;
        case 3: src = w3; break; case 4: src = w4; break; case 5: src = w5; break;
        case 6: src = w6; break; case 7: src = w7; break; default: src = w8; break;
    }
    g_w[seg * 65536 + idx] = f2tff(src[idx]);
}

// ---------------- downsample -> [B,C,Np], pad cols zero ----------------
__global__ void ds_kernel(const float* __restrict__ zr, const float* __restrict__ zi) {
    int idx = blockIdx.x * blockDim.x + threadIdx.x;
    if (idx >= Bb*Cc*NTP) return;
    int n = idx % NTP, bc = idx / NTP;
    if (n >= NT) { g_ds_rgb[idx] = 0.f; g_ds_ir[idx] = 0.f; return; }
    int ho = n / WDs, wo = n % WDs;
    int base = (bc * HH + 4 * ho + 1) * WW + 4 * wo + 1;
    g_ds_rgb[idx] = f2tff(0.25f * (zr[base] + zr[base+1] + zr[base+WW] + zr[base+WW+1]));
    g_ds_ir [idx] = f2tff(0.25f * (zi[base] + zi[base+1] + zi[base+WW] + zi[base+WW+1]));
}

// ---------------- projections ----------------
__global__ void __launch_bounds__(256) proj_gemm(
    const float* __restrict__ bq_rgb, const float* __restrict__ bk_ir,
    const float* __restrict__ bv_ir,  const float* __restrict__ bq_ir,
    const float* __restrict__ bk_rgb, const float* __restrict__ bv_rgb)
{
    extern __shared__ float sm[];
    int b = blockIdx.x / NBLK, mloc = (blockIdx.x % NBLK) * 128;
    int n0 = blockIdx.y * 128, p = blockIdx.z;
    const float* Ain = (p == 0 || p == 4 || p == 5) ? g_ds_rgb : g_ds_ir;
    const float* bias;
    switch (p) {
        case 0: bias = bq_rgb; break; case 1: bias = bk_ir;  break;
        case 2: bias = bv_ir;  break; case 3: bias = bq_ir;  break;
        case 4: bias = bk_rgb; break; default: bias = bv_rgb; break;
    }
    const float* A = Ain + (size_t)b * Cc * NTP + mloc;
    const float* W = g_w + p * 65536 + (size_t)n0 * Cc;

    float acc[2][8][4] = {};
    gemm128_tf32<1, 0>(A, NTP, W, Cc, Cc, acc, sm);

    const int tid = threadIdx.x, lane = tid & 31, warp = tid >> 5;
    const int wm = (warp >> 1) * 32, wn = (warp & 1) * 64;
    const int g = lane >> 2, tg = lane & 3;
    float* out = g_tok[p];
#pragma unroll
    for (int mi = 0; mi < 2; mi++) {
        int rl = mloc + wm + mi * 16 + g;
#pragma unroll
        for (int ni = 0; ni < 8; ni++) {
            int col = n0 + wn + ni * 8 + 2 * tg;
            float b0 = bias[col], b1 = bias[col + 1];
            if (rl < NT) {
                float2 v = { f2tff(acc[mi][ni][0] + b0), f2tff(acc[mi][ni][1] + b1) };
                *(float2*)(out + ((size_t)b * NT + rl) * Cc + col) = v;
            }
            if (rl + 8 < NT) {
                float2 v = { f2tff(acc[mi][ni][2] + b0), f2tff(acc[mi][ni][3] + b1) };
                *(float2*)(out + ((size_t)b * NT + rl + 8) * Cc + col) = v;
            }
        }
    }
}

// ---------------- scores: attn = exp((Q K^T)/16) tf32-f32, partial rowsums ----------
__global__ void __launch_bounds__(256) scores_gemm() {
    extern __shared__ float sm[];
    __shared__ float rsum[128];
    int m0 = blockIdx.x * 128, n0 = blockIdx.y * 128;
    int z = blockIdx.z, dir = z >> 3, b = z & 7;
    const float* Aq = g_tok[dir ? 3 : 0] + ((size_t)b * NT + m0) * Cc;
    const float* Bk = g_tok[dir ? 4 : 1] + ((size_t)b * NT + n0) * Cc;
    float* out = (dir ? g_attn1 : g_attn0) + ((size_t)b * NT + m0) * ATW + n0;

    if (threadIdx.x < 128) rsum[threadIdx.x] = 0.f;
    float acc[2][8][4] = {};
    gemm128_tf32<0, 0>(Aq, Cc, Bk, Cc, Cc, acc, sm);

    const int tid = threadIdx.x, lane = tid & 31, warp = tid >> 5;
    const int wm = (warp >> 1) * 32, wn = (warp & 1) * 64;
    const int g = lane >> 2, tg = lane & 3;
#pragma unroll
    for (int mi = 0; mi < 2; mi++) {
        int r0 = wm + mi * 16 + g;
        bool ok0 = (m0 + r0) < NT, ok1 = (m0 + r0 + 8) < NT;
        float p0 = 0.f, p1 = 0.f;
#pragma unroll
        for (int ni = 0; ni < 8; ni++) {
            int col = wn + ni * 8 + 2 * tg;
            bool real = (n0 + col) < NT;
            float e0 = real ? __expf(acc[mi][ni][0] * 0.0625f) : 0.f;
            float e1 = real ? __expf(acc[mi][ni][1] * 0.0625f) : 0.f;
            float e2 = real ? __expf(acc[mi][ni][2] * 0.0625f) : 0.f;
            float e3 = real ? __expf(acc[mi][ni][3] * 0.0625f) : 0.f;
            if (ok0) *(float2*)(out + (size_t)r0 * ATW + col) =
                make_float2(f2tff(e0), f2tff(e1));
            if (ok1) *(float2*)(out + (size_t)(r0 + 8) * ATW + col) =
                make_float2(f2tff(e2), f2tff(e3));
            p0 += e0 + e1;
            p1 += e2 + e3;
        }
        p0 += __shfl_xor_sync(0xffffffffu, p0, 1); p0 += __shfl_xor_sync(0xffffffffu, p0, 2);
        p1 += __shfl_xor_sync(0xffffffffu, p1, 1); p1 += __shfl_xor_sync(0xffffffffu, p1, 2);
        if (tg == 0) {
            atomicAdd(&rsum[r0], p0);
            atomicAdd(&rsum[r0 + 8], p1);
        }
    }
    __syncthreads();
    if (tid < 128 && (m0 + tid) < NT)
        g_psum[((size_t)z * NT + m0 + tid) * NBLK + blockIdx.y] = rsum[tid];
}

// ---------------- rowsum reduce ----------------
__global__ void rowinv_kernel() {
    int idx = blockIdx.x * blockDim.x + threadIdx.x;
    if (idx >= 2 * Bb * NT) return;
    float s = 0.f;
    const float* p = g_psum + (size_t)idx * NBLK;
#pragma unroll
    for (int j = 0; j < NBLK; j++) s += p[j];
    g_rowinv[idx] = 1.0f / s;
}

// ---------------- attn @ V (tf32, V tok-major [k][n]), normalized -> zcat ----------
__global__ void __launch_bounds__(256) av_gemm() {
    extern __shared__ float sm[];
    int m0 = blockIdx.x * 128, n0 = blockIdx.y * 128;
    int z = blockIdx.z, dir = z >> 3, b = z & 7;
    const float* P = (dir ? g_attn1 : g_attn0) + ((size_t)b * NT + m0) * ATW;
    const float* V = g_tok[dir ? 5 : 2] + (size_t)b * NT * Cc + n0;   // [k][n], ldb=Cc

    float acc[2][8][4] = {};
    gemm128_tf32<0, 1>(P, ATW, V, Cc, ATW, acc, sm);

    const int tid = threadIdx.x, lane = tid & 31, warp = tid >> 5;
    const int wm = (warp >> 1) * 32, wn = (warp & 1) * 64;
    const int g = lane >> 2, tg = lane & 3;
    float* out = g_zcat + (size_t)b * NT * 2 * Cc + dir * Cc + n0;
    const float* rinv = g_rowinv + (size_t)z * NT + m0;
#pragma unroll
    for (int mi = 0; mi < 2; mi++) {
        int r0 = wm + mi * 16 + g;
        bool ok0 = (m0 + r0) < NT, ok1 = (m0 + r0 + 8) < NT;
        float i0 = ok0 ? rinv[r0] : 0.f;
        float i1 = ok1 ? rinv[r0 + 8] : 0.f;
#pragma unroll
        for (int ni = 0; ni < 8; ni++) {
            int col = wn + ni * 8 + 2 * tg;
            if (ok0) {
                float2 v = { f2tff(acc[mi][ni][0] * i0), f2tff(acc[mi][ni][1] * i0) };
                *(float2*)(out + (size_t)(m0 + r0) * 2 * Cc + col) = v;
            }
            if (ok1) {
                float2 v = { f2tff(acc[mi][ni][2] * i1), f2tff(acc[mi][ni][3] * i1) };
                *(float2*)(out + (size_t)(m0 + r0 + 8) * 2 * Cc + col) = v;
            }
        }
    }
}

// ---------------- epilogue GEMMs ----------------
__global__ void __launch_bounds__(256) final_gemm(
    const float* __restrict__ brgb, const float* __restrict__ bir,
    const float* __restrict__ bz) {
    extern __shared__ float sm[];
    int m0 = blockIdx.x * 128, n0 = blockIdx.y * 128, jj = blockIdx.z;
    const float* A = g_zcat + (size_t)m0 * 2 * Cc + (jj == 1 ? Cc : 0);
    int Kd = (jj == 2) ? 2 * Cc : Cc;
    const float* W    = (jj == 2) ? (g_w + 524288) : (g_w + (6 + jj) * 65536);
    const float* bias = (jj == 0) ? brgb : ((jj == 1) ? bir : bz);

    float acc[2][8][4] = {};
    gemm128_tf32<0, 0>(A, 2 * Cc, W + (size_t)n0 * Kd, Kd, Kd, acc, sm);

    const int tid = threadIdx.x, lane = tid & 31, warp = tid >> 5;
    const int wm = (warp >> 1) * 32, wn = (warp & 1) * 64;
    const int g = lane >> 2, tg = lane & 3;
    float* out = g_pre[jj] + (size_t)m0 * Cc + n0;
#pragma unroll
    for (int mi = 0; mi < 2; mi++) {
        int r0 = wm + mi * 16 + g;
#pragma unroll
        for (int ni = 0; ni < 8; ni++) {
            int col = wn + ni * 8 + 2 * tg;
            float b0 = bias[n0 + col], b1 = bias[n0 + col + 1];
            float2 v0 = { acc[mi][ni][0] + b0, acc[mi][ni][1] + b1 };
            float2 v1 = { acc[mi][ni][2] + b0, acc[mi][ni][3] + b1 };
            *(float2*)(out + (size_t)r0 * Cc + col) = v0;
            *(float2*)(out + (size_t)(r0 + 8) * Cc + col) = v1;
        }
    }
}

// ---------------- gate fuse + smem transpose to [B,C,N] ----------------
__global__ void fuse_kernel(const int* __restrict__ time_idx, const float* __restrict__ temb) {
    __shared__ float t[32][33];
    int b = blockIdx.z;
    int n0 = blockIdx.x * 32, c0 = blockIdx.y * 32;
    int tx = threadIdx.x, ty = threadIdx.y;
    int ti = time_idx[b];
#pragma unroll
    for (int i = 0; i < 4; i++) {
        int n = n0 + ty + 8 * i, c = c0 + tx;
        size_t m = ((size_t)b * NT + n) * Cc + c;
        float hr = tanhf(g_pre[0][m]);
        float hi = tanhf(g_pre[1][m]);
        float zb = 1.0f / (1.0f + __expf(-g_pre[2][m]));
        float te = temb[ti * Cc + c];
        float zf = 1.0f / (1.0f + __expf(-(zb + te)));
        t[ty + 8 * i][tx] = zf * hr + (1.0f - zf) * hi;
    }
    __syncthreads();
#pragma unroll
    for (int i = 0; i < 4; i++) {
        int c = c0 + ty + 8 * i, n = n0 + tx;
        g_fused[((size_t)b * Cc + c) * NT + n] = t[tx][ty + 8 * i];
    }
}

// ---------------- bilinear upsample 40 -> 160 ----------------
__global__ void upsample_kernel(float* __restrict__ out) {
    int idx = blockIdx.x * blockDim.x + threadIdx.x;
    if (idx >= Bb*Cc*HH*WW) return;
    int w  = idx % WW;
    int h  = (idx / WW) % HH;
    int bc = idx / (HH * WW);
    float sh = fmaxf(h * 0.25f - 0.375f, 0.0f);
    float sw = fmaxf(w * 0.25f - 0.375f, 0.0f);
    int h0 = (int)sh; float fh = sh - (float)h0; int h1 = min(h0 + 1, HDs - 1);
    int w0 = (int)sw; float fw = sw - (float)w0; int w1 = min(w0 + 1, WDs - 1);
    const float* p = g_fused + (size_t)bc * NT;
    float v00 = p[h0 * WDs + w0], v01 = p[h0 * WDs + w1];
    float v10 = p[h1 * WDs + w0], v11 = p[h1 * WDs + w1];
    float top = v00 * (1.0f - fw) + v01 * fw;
    float bot = v10 * (1.0f - fw) + v11 * fw;
    out[idx] = top * (1.0f - fh) + bot * fh;
}

extern "C" void kernel_launch(void* const* d_in, const int* in_sizes, int n_in,
                              void* d_out, int out_size) {
    const float* z_rgb  = (const float*)d_in[0];
    const float* z_ir   = (const float*)d_in[1];
    const int*   tidx   = (const int*)  d_in[2];
    const float* Wq_rgb = (const float*)d_in[3],  *bq_rgb = (const float*)d_in[4];
    const float* Wk_ir  = (const float*)d_in[5],  *bk_ir  = (const float*)d_in[6];
    const float* Wv_ir  = (const float*)d_in[7],  *bv_ir  = (const float*)d_in[8];
    const float* Wq_ir  = (const float*)d_in[9],  *bq_ir  = (const float*)d_in[10];
    const float* Wk_rgb = (const float*)d_in[11], *bk_rgb = (const float*)d_in[12];
    const float* Wv_rgb = (const float*)d_in[13], *bv_rgb = (const float*)d_in[14];
    const float* Wrgb   = (const float*)d_in[15], *brgb   = (const float*)d_in[16];
    const float* Wir    = (const float*)d_in[17], *bir    = (const float*)d_in[18];
    const float* Wz     = (const float*)d_in[19], *bz     = (const float*)d_in[20];
    const float* temb   = (const float*)d_in[21];

    static bool attr_done = false;
    if (!attr_done) {
        cudaFuncSetAttribute(proj_gemm,   cudaFuncAttributeMaxDynamicSharedMemorySize, SMEM_T);
        cudaFuncSetAttribute(scores_gemm, cudaFuncAttributeMaxDynamicSharedMemorySize, SMEM_T);
        cudaFuncSetAttribute(av_gemm,     cudaFuncAttributeMaxDynamicSharedMemorySize, SMEM_T);
        cudaFuncSetAttribute(final_gemm,  cudaFuncAttributeMaxDynamicSharedMemorySize, SMEM_T);
        attr_done = true;
    }

    wprep_kernel<<<dim3(512, 9), 256>>>(Wq_rgb, Wk_ir, Wv_ir, Wq_ir, Wk_rgb, Wv_rgb,
                                        Wrgb, Wir, Wz);
    ds_kernel<<<(Bb*Cc*NTP + 255) / 256, 256>>>(z_rgb, z_ir);
    proj_gemm<<<dim3(NBLK * Bb, 2, 6), 256, SMEM_T>>>(bq_rgb, bk_ir, bv_ir, bq_ir, bk_rgb, bv_rgb);
    scores_gemm<<<dim3(NBLK, NBLK, 16), 256, SMEM_T>>>();
    rowinv_kernel<<<(2*Bb*NT + 255) / 256, 256>>>();
    av_gemm<<<dim3(NBLK, 2, 16), 256, SMEM_T>>>();
    final_gemm<<<dim3(100, 2, 3), 256, SMEM_T>>>(brgb, bir, bz);
    fuse_kernel<<<dim3(NT/32, Cc/32, Bb), dim3(32, 8)>>>(tidx, temb);
    upsample_kernel<<<(Bb*Cc*HH*WW + 255) / 256, 256>>>((float*)d_out);
}

// round 8
// speedup vs baseline: 1.2883x; 1.2883x over previous
#include <cuda_runtime.h>
#include <cuda_fp16.h>
#include <math.h>
#include <float.h>
#include <stdint.h>

#define Bb  8
#define Cc  256
#define HH  160
#define WW  160
#define HDs 40
#define WDs 40
#define NT  1600
#define MT  (Bb*NT)
#define ATW 1664            // padded attention width (13*128)
#define NBLK 13
#define SA  40              // smem row stride in halves (32 + 8 pad, 16B-aligned)

// ---------------- static scratch ----------------
__device__ __align__(256) __half g_ds_rgb[(size_t)Bb*NT*Cc];     // token-major [b][n][c]
__device__ __align__(256) __half g_ds_ir [(size_t)Bb*NT*Cc];
__device__ __align__(256) __half g_tok[6][(size_t)(MT+64)*Cc];   // [b*NT+n][c] (+zero tail)
__device__ __align__(256) __half g_attn0[(size_t)MT*ATW];        // exp(scores), pad cols 0
__device__ __align__(256) __half g_attn1[(size_t)MT*ATW];
__device__ __align__(256) __half g_vT[2][(size_t)Bb*Cc*ATW];     // [dir][b][c][tok], pad 0
__device__ __align__(256) __half g_zcat[(size_t)MT*2*Cc];        // [b*NT+n][2C]
__device__ __align__(256) __half g_wh[655360];                   // fp16 weights
__device__ float g_psum[2*Bb*NT*NBLK];
__device__ float g_rowinv[2*Bb*NT];
__device__ float g_pre[3][(size_t)MT*Cc];
__device__ float g_fused[(size_t)Bb*Cc*NT];

__device__ __forceinline__ void cpa16(const void* smem_dst, const void* gsrc) {
    uint32_t s = (uint32_t)__cvta_generic_to_shared(smem_dst);
    asm volatile("cp.async.cg.shared.global [%0], [%1], 16;" :: "r"(s), "l"(gsrc));
}

// ======== fp16 GEMM core: 64(M) x 128(N) block, 128 threads, warp tile 32x64 ========
// A: [m][k] halves (lda), B: [n][k] halves (ldb); K multiple of 32; fp32 accum.
__device__ __forceinline__ void gemm64_fp16(
    const __half* __restrict__ A, int lda,
    const __half* __restrict__ B, int ldb,
    int K, float acc[2][8][4])
{
    __shared__ __align__(16) __half As[2][64*SA];
    __shared__ __align__(16) __half Bs[2][128*SA];
    const int tid = threadIdx.x, lane = tid & 31, warp = tid >> 5;
    const int wm = (warp >> 1) * 32, wn = (warp & 1) * 64;
    const int g = lane >> 2, tg = lane & 3;

    auto issue = [&](int k0, int bi) {
#pragma unroll
        for (int i = 0; i < 2; i++) {                 // A: 64 rows x 4 16B-chunks
            int idx = tid + i * 128;
            int row = idx >> 2, kg = (idx & 3) * 8;
            cpa16(&As[bi][row * SA + kg], A + (size_t)row * lda + k0 + kg);
        }
#pragma unroll
        for (int i = 0; i < 4; i++) {                 // B: 128 rows x 4 chunks
            int idx = tid + i * 128;
            int row = idx >> 2, kg = (idx & 3) * 8;
            cpa16(&Bs[bi][row * SA + kg], B + (size_t)row * ldb + k0 + kg);
        }
        asm volatile("cp.async.commit_group;");
    };

    issue(0, 0);
    int buf = 0;
    for (int k0 = 0; k0 < K; k0 += 32) {
        asm volatile("cp.async.wait_group 0;");
        __syncthreads();
        if (k0 + 32 < K) issue(k0 + 32, buf ^ 1);
        const __half* as = As[buf];
        const __half* bs = Bs[buf];
#pragma unroll
        for (int s = 0; s < 2; s++) {
            const int kk = s * 16;
            unsigned a[2][4], b[8][2];
#pragma unroll
            for (int mi = 0; mi < 2; mi++) {
                int r = wm + mi * 16 + g;
                a[mi][0] = *(const unsigned*)&as[r * SA + kk + 2 * tg];
                a[mi][1] = *(const unsigned*)&as[(r + 8) * SA + kk + 2 * tg];
                a[mi][2] = *(const unsigned*)&as[r * SA + kk + 8 + 2 * tg];
                a[mi][3] = *(const unsigned*)&as[(r + 8) * SA + kk + 8 + 2 * tg];
            }
#pragma unroll
            for (int ni = 0; ni < 8; ni++) {
                int n = wn + ni * 8 + g;
                b[ni][0] = *(const unsigned*)&bs[n * SA + kk + 2 * tg];
                b[ni][1] = *(const unsigned*)&bs[n * SA + kk + 8 + 2 * tg];
            }
#pragma unroll
            for (int mi = 0; mi < 2; mi++)
#pragma unroll
                for (int ni = 0; ni < 8; ni++) {
                    asm volatile(
                        "mma.sync.aligned.m16n8k16.row.col.f32.f16.f16.f32 "
                        "{%0,%1,%2,%3}, {%4,%5,%6,%7}, {%8,%9}, {%0,%1,%2,%3};"
                        : "+f"(acc[mi][ni][0]), "+f"(acc[mi][ni][1]),
                          "+f"(acc[mi][ni][2]), "+f"(acc[mi][ni][3])
                        : "r"(a[mi][0]), "r"(a[mi][1]), "r"(a[mi][2]), "r"(a[mi][3]),
                          "r"(b[ni][0]), "r"(b[ni][1]));
                }
        }
        buf ^= 1;
    }
}

// ---------------- weight prep: fp32 -> fp16 ----------------
__global__ void wprep_kernel(
    const float* w0, const float* w1, const float* w2, const float* w3,
    const float* w4, const float* w5, const float* w6, const float* w7, const float* w8)
{
    int seg = blockIdx.y;
    int idx = blockIdx.x * 256 + threadIdx.x;
    int size = (seg == 8) ? 131072 : 65536;
    if (idx >= size) return;
    const float* src;
    switch (seg) {
        case 0: src = w0; break; case 1: src = w1; break; case 2: src = w2; break;
        case 3: src = w3; break; case 4: src = w4; break; case 5: src = w5; break;
        case 6: src = w6; break; case 7: src = w7; break; default: src = w8; break;
    }
    g_wh[seg * 65536 + idx] = __float2half_rn(src[idx]);
}

// ---------------- downsample: 2x2 mean -> token-major fp16 [b][n][c] ----------------
__global__ void ds_kernel(const float* __restrict__ zr, const float* __restrict__ zi) {
    __shared__ float t[32][33];
    int b = blockIdx.z, n0 = blockIdx.x * 32, c0 = blockIdx.y * 32;
    int tx = threadIdx.x, ty = threadIdx.y;
#pragma unroll
    for (int m = 0; m < 2; m++) {
        const float* src = m ? zi : zr;
        __half* dst = m ? g_ds_ir : g_ds_rgb;
        if (m) __syncthreads();
#pragma unroll
        for (int i = 0; i < 4; i++) {
            int n = n0 + tx, c = c0 + ty + 8 * i;
            int ho = n / WDs, wo = n % WDs;
            const float* p = src + ((size_t)(b * Cc + c) * HH + 4 * ho + 1) * WW + 4 * wo + 1;
            t[tx][ty + 8 * i] = 0.25f * (p[0] + p[1] + p[WW] + p[WW + 1]);
        }
        __syncthreads();
#pragma unroll
        for (int i = 0; i < 4; i++) {
            int n = n0 + ty + 8 * i, c = c0 + tx;
            dst[((size_t)b * NT + n) * Cc + c] = __float2half_rn(t[ty + 8 * i][tx]);
        }
    }
}

// ---------------- projections: out = ds @ W^T + bias ----------------
__global__ void __launch_bounds__(128) proj_gemm(
    const float* __restrict__ bq_rgb, const float* __restrict__ bk_ir,
    const float* __restrict__ bv_ir,  const float* __restrict__ bq_ir,
    const float* __restrict__ bk_rgb, const float* __restrict__ bv_rgb)
{
    int b = blockIdx.x / 25, mloc = (blockIdx.x % 25) * 64;
    int n0 = blockIdx.y * 128, p = blockIdx.z;
    const __half* Ain = (p == 0 || p == 4 || p == 5) ? g_ds_rgb : g_ds_ir;
    const float* bias;
    switch (p) {
        case 0: bias = bq_rgb; break; case 1: bias = bk_ir;  break;
        case 2: bias = bv_ir;  break; case 3: bias = bq_ir;  break;
        case 4: bias = bk_rgb; break; default: bias = bv_rgb; break;
    }
    const __half* A = Ain + ((size_t)b * NT + mloc) * Cc;
    const __half* W = g_wh + p * 65536 + (size_t)n0 * Cc;
    float acc[2][8][4] = {};
    gemm64_fp16(A, Cc, W, Cc, Cc, acc);

    const int tid = threadIdx.x, lane = tid & 31, warp = tid >> 5;
    const int wm = (warp >> 1) * 32, wn = (warp & 1) * 64;
    const int g = lane >> 2, tg = lane & 3;
    __half* out = g_tok[p] + ((size_t)b * NT + mloc) * Cc + n0;
#pragma unroll
    for (int mi = 0; mi < 2; mi++) {
        int r0 = wm + mi * 16 + g;
#pragma unroll
        for (int ni = 0; ni < 8; ni++) {
            int col = wn + ni * 8 + 2 * tg;
            float b0 = bias[n0 + col], b1 = bias[n0 + col + 1];
            *(__half2*)(out + (size_t)r0 * Cc + col) =
                __floats2half2_rn(acc[mi][ni][0] + b0, acc[mi][ni][1] + b1);
            *(__half2*)(out + (size_t)(r0 + 8) * Cc + col) =
                __floats2half2_rn(acc[mi][ni][2] + b0, acc[mi][ni][3] + b1);
        }
    }
}

// ---------------- V transpose: [dir][b][c][tok] fp16, pad tokens 0 ----------------
__global__ void vprep_kernel() {
    __shared__ float t[32][33];
    int z = blockIdx.z, dir = z >> 3, b = z & 7;
    int n0 = blockIdx.x * 32, c0 = blockIdx.y * 32;
    int tx = threadIdx.x, ty = threadIdx.y;
    const __half* tok = g_tok[dir ? 5 : 2];
#pragma unroll
    for (int i = 0; i < 4; i++) {
        int n = n0 + ty + 8 * i, c = c0 + tx;
        t[ty + 8 * i][tx] = (n < NT) ? __half2float(tok[((size_t)b * NT + n) * Cc + c]) : 0.f;
    }
    __syncthreads();
#pragma unroll
    for (int i = 0; i < 4; i++) {
        int c = c0 + ty + 8 * i, n = n0 + tx;
        g_vT[dir][((size_t)b * Cc + c) * ATW + n] = __float2half_rn(t[tx][ty + 8 * i]);
    }
}

// ---------------- scores: attn = exp((Q K^T)/16) fp16, partial rowsums ----------------
__global__ void __launch_bounds__(128) scores_gemm() {
    __shared__ float rsum[64];
    int m0 = blockIdx.x * 64, n0 = blockIdx.y * 128;
    int z = blockIdx.z, dir = z >> 3, b = z & 7;
    const __half* Aq = g_tok[dir ? 3 : 0] + ((size_t)b * NT + m0) * Cc;
    const __half* Bk = g_tok[dir ? 4 : 1] + ((size_t)b * NT + n0) * Cc;
    __half* out = (dir ? g_attn1 : g_attn0) + ((size_t)b * NT + m0) * ATW + n0;

    if (threadIdx.x < 64) rsum[threadIdx.x] = 0.f;
    float acc[2][8][4] = {};
    gemm64_fp16(Aq, Cc, Bk, Cc, Cc, acc);

    const int tid = threadIdx.x, lane = tid & 31, warp = tid >> 5;
    const int wm = (warp >> 1) * 32, wn = (warp & 1) * 64;
    const int g = lane >> 2, tg = lane & 3;
#pragma unroll
    for (int mi = 0; mi < 2; mi++) {
        int r0 = wm + mi * 16 + g;
        float p0 = 0.f, p1 = 0.f;
#pragma unroll
        for (int ni = 0; ni < 8; ni++) {
            int col = wn + ni * 8 + 2 * tg;
            bool real = (n0 + col) < NT;
            float e0 = real ? __expf(acc[mi][ni][0] * 0.0625f) : 0.f;
            float e1 = real ? __expf(acc[mi][ni][1] * 0.0625f) : 0.f;
            float e2 = real ? __expf(acc[mi][ni][2] * 0.0625f) : 0.f;
            float e3 = real ? __expf(acc[mi][ni][3] * 0.0625f) : 0.f;
            *(__half2*)(out + (size_t)r0 * ATW + col) = __floats2half2_rn(e0, e1);
            *(__half2*)(out + (size_t)(r0 + 8) * ATW + col) = __floats2half2_rn(e2, e3);
            p0 += e0 + e1;
            p1 += e2 + e3;
        }
        p0 += __shfl_xor_sync(0xffffffffu, p0, 1); p0 += __shfl_xor_sync(0xffffffffu, p0, 2);
        p1 += __shfl_xor_sync(0xffffffffu, p1, 1); p1 += __shfl_xor_sync(0xffffffffu, p1, 2);
        if (tg == 0) {
            atomicAdd(&rsum[r0], p0);
            atomicAdd(&rsum[r0 + 8], p1);
        }
    }
    __syncthreads();
    if (tid < 64)
        g_psum[((size_t)z * NT + m0 + tid) * NBLK + blockIdx.y] = rsum[tid];
}

// ---------------- rowsum reduce ----------------
__global__ void rowinv_kernel() {
    int idx = blockIdx.x * blockDim.x + threadIdx.x;
    if (idx >= 2 * Bb * NT) return;
    float s = 0.f;
    const float* p = g_psum + (size_t)idx * NBLK;
#pragma unroll
    for (int j = 0; j < NBLK; j++) s += p[j];
    g_rowinv[idx] = 1.0f / s;
}

// ---------------- attn @ V (fp16), normalized -> zcat fp16 ----------------
__global__ void __launch_bounds__(128) av_gemm() {
    int m0 = blockIdx.x * 64, n0 = blockIdx.y * 128;
    int z = blockIdx.z, dir = z >> 3, b = z & 7;
    const __half* P = (dir ? g_attn1 : g_attn0) + ((size_t)b * NT + m0) * ATW;
    const __half* V = g_vT[dir] + ((size_t)b * Cc + n0) * ATW;
    float acc[2][8][4] = {};
    gemm64_fp16(P, ATW, V, ATW, ATW, acc);

    const int tid = threadIdx.x, lane = tid & 31, warp = tid >> 5;
    const int wm = (warp >> 1) * 32, wn = (warp & 1) * 64;
    const int g = lane >> 2, tg = lane & 3;
    __half* out = g_zcat + ((size_t)b * NT + m0) * 2 * Cc + dir * Cc + n0;
    const float* rinv = g_rowinv + (size_t)z * NT + m0;
#pragma unroll
    for (int mi = 0; mi < 2; mi++) {
        int r0 = wm + mi * 16 + g;
        float i0 = rinv[r0], i1 = rinv[r0 + 8];
#pragma unroll
        for (int ni = 0; ni < 8; ni++) {
            int col = wn + ni * 8 + 2 * tg;
            *(__half2*)(out + (size_t)r0 * 2 * Cc + col) =
                __floats2half2_rn(acc[mi][ni][0] * i0, acc[mi][ni][1] * i0);
            *(__half2*)(out + (size_t)(r0 + 8) * 2 * Cc + col) =
                __floats2half2_rn(acc[mi][ni][2] * i1, acc[mi][ni][3] * i1);
        }
    }
}

// ---------------- epilogue GEMMs -> fp32 pre-activations ----------------
__global__ void __launch_bounds__(128) final_gemm(
    const float* __restrict__ brgb, const float* __restrict__ bir, const float* __restrict__ bz)
{
    int m0 = blockIdx.x * 64, n0 = blockIdx.y * 128, jj = blockIdx.z;
    const __half* A = g_zcat + (size_t)m0 * 2 * Cc + (jj == 1 ? Cc : 0);
    int Kd = (jj == 2) ? 2 * Cc : Cc;
    const __half* W    = (jj == 2) ? (g_wh + 524288) : (g_wh + (6 + jj) * 65536);
    const float* bias = (jj == 0) ? brgb : ((jj == 1) ? bir : bz);
    float acc[2][8][4] = {};
    gemm64_fp16(A, 2 * Cc, W + (size_t)n0 * Kd, Kd, Kd, acc);

    const int tid = threadIdx.x, lane = tid & 31, warp = tid >> 5;
    const int wm = (warp >> 1) * 32, wn = (warp & 1) * 64;
    const int g = lane >> 2, tg = lane & 3;
    float* out = g_pre[jj] + (size_t)m0 * Cc + n0;
#pragma unroll
    for (int mi = 0; mi < 2; mi++) {
        int r0 = wm + mi * 16 + g;
#pragma unroll
        for (int ni = 0; ni < 8; ni++) {
            int col = wn + ni * 8 + 2 * tg;
            float b0 = bias[n0 + col], b1 = bias[n0 + col + 1];
            float2 v0 = { acc[mi][ni][0] + b0, acc[mi][ni][1] + b1 };
            float2 v1 = { acc[mi][ni][2] + b0, acc[mi][ni][3] + b1 };
            *(float2*)(out + (size_t)r0 * Cc + col) = v0;
            *(float2*)(out + (size_t)(r0 + 8) * Cc + col) = v1;
        }
    }
}

// ---------------- gate fuse + smem transpose to [B,C,N] ----------------
__global__ void fuse_kernel(const int* __restrict__ time_idx, const float* __restrict__ temb) {
    __shared__ float t[32][33];
    int b = blockIdx.z;
    int n0 = blockIdx.x * 32, c0 = blockIdx.y * 32;
    int tx = threadIdx.x, ty = threadIdx.y;
    int ti = time_idx[b];
#pragma unroll
    for (int i = 0; i < 4; i++) {
        int n = n0 + ty + 8 * i, c = c0 + tx;
        size_t m = ((size_t)b * NT + n) * Cc + c;
        float hr = tanhf(g_pre[0][m]);
        float hi = tanhf(g_pre[1][m]);
        float zb = 1.0f / (1.0f + __expf(-g_pre[2][m]));
        float te = temb[ti * Cc + c];
        float zf = 1.0f / (1.0f + __expf(-(zb + te)));
        t[ty + 8 * i][tx] = zf * hr + (1.0f - zf) * hi;
    }
    __syncthreads();
#pragma unroll
    for (int i = 0; i < 4; i++) {
        int c = c0 + ty + 8 * i, n = n0 + tx;
        g_fused[((size_t)b * Cc + c) * NT + n] = t[tx][ty + 8 * i];
    }
}

// ---------------- bilinear upsample 40 -> 160 ----------------
__global__ void upsample_kernel(float* __restrict__ out) {
    int idx = blockIdx.x * blockDim.x + threadIdx.x;
    if (idx >= Bb*Cc*HH*WW) return;
    int w  = idx % WW;
    int h  = (idx / WW) % HH;
    int bc = idx / (HH * WW);
    float sh = fmaxf(h * 0.25f - 0.375f, 0.0f);
    float sw = fmaxf(w * 0.25f - 0.375f, 0.0f);
    int h0 = (int)sh; float fh = sh - (float)h0; int h1 = min(h0 + 1, HDs - 1);
    int w0 = (int)sw; float fw = sw - (float)w0; int w1 = min(w0 + 1, WDs - 1);
    const float* p = g_fused + (size_t)bc * NT;
    float v00 = p[h0 * WDs + w0], v01 = p[h0 * WDs + w1];
    float v10 = p[h1 * WDs + w0], v11 = p[h1 * WDs + w1];
    float top = v00 * (1.0f - fw) + v01 * fw;
    float bot = v10 * (1.0f - fw) + v11 * fw;
    out[idx] = top * (1.0f - fh) + bot * fh;
}

extern "C" void kernel_launch(void* const* d_in, const int* in_sizes, int n_in,
                              void* d_out, int out_size) {
    const float* z_rgb  = (const float*)d_in[0];
    const float* z_ir   = (const float*)d_in[1];
    const int*   tidx   = (const int*)  d_in[2];
    const float* Wq_rgb = (const float*)d_in[3],  *bq_rgb = (const float*)d_in[4];
    const float* Wk_ir  = (const float*)d_in[5],  *bk_ir  = (const float*)d_in[6];
    const float* Wv_ir  = (const float*)d_in[7],  *bv_ir  = (const float*)d_in[8];
    const float* Wq_ir  = (const float*)d_in[9],  *bq_ir  = (const float*)d_in[10];
    const float* Wk_rgb = (const float*)d_in[11], *bk_rgb = (const float*)d_in[12];
    const float* Wv_rgb = (const float*)d_in[13], *bv_rgb = (const float*)d_in[14];
    const float* Wrgb   = (const float*)d_in[15], *brgb   = (const float*)d_in[16];
    const float* Wir    = (const float*)d_in[17], *bir    = (const float*)d_in[18];
    const float* Wz     = (const float*)d_in[19], *bz     = (const float*)d_in[20];
    const float* temb   = (const float*)d_in[21];

    wprep_kernel<<<dim3(512, 9), 256>>>(Wq_rgb, Wk_ir, Wv_ir, Wq_ir, Wk_rgb, Wv_rgb,
                                        Wrgb, Wir, Wz);
    ds_kernel<<<dim3(50, 8, 8), dim3(32, 8)>>>(z_rgb, z_ir);
    proj_gemm<<<dim3(200, 2, 6), 128>>>(bq_rgb, bk_ir, bv_ir, bq_ir, bk_rgb, bv_rgb);
    vprep_kernel<<<dim3(52, 8, 16), dim3(32, 8)>>>();
    scores_gemm<<<dim3(25, NBLK, 16), 128>>>();
    rowinv_kernel<<<(2*Bb*NT + 255) / 256, 256>>>();
    av_gemm<<<dim3(25, 2, 16), 128>>>();
    final_gemm<<<dim3(200, 2, 3), 128>>>(brgb, bir, bz);
    fuse_kernel<<<dim3(NT/32, Cc/32, Bb), dim3(32, 8)>>>(tidx, temb);
    upsample_kernel<<<(Bb*Cc*HH*WW + 255) / 256, 256>>>((float*)d_out);
}

// round 9
// speedup vs baseline: 1.3000x; 1.0091x over previous
#include <cuda_runtime.h>
#include <cuda_fp16.h>
#include <math.h>
#include <float.h>
#include <stdint.h>

#define Bb  8
#define Cc  256
#define HH  160
#define WW  160
#define HDs 40
#define WDs 40
#define NT  1600
#define MT  (Bb*NT)
#define ATW 1664            // padded attention width (13*128)
#define NBLK 13
#define SA  40              // smem row stride (halves) for [r][k] tiles
#define SN  136             // smem row stride (halves) for [k][n] tiles (128+8)
#define BSW 5120            // B smem halves per buffer: max(128*40, 32*136)

// ---------------- static scratch ----------------
__device__ __align__(256) __half g_ds_rgb[(size_t)Bb*NT*Cc];     // token-major [b][n][c]
__device__ __align__(256) __half g_ds_ir [(size_t)Bb*NT*Cc];
__device__ __align__(256) __half g_tok[6][(size_t)(MT+64)*Cc];   // [b*NT+n][c] (+zero tail)
__device__ __align__(256) __half g_attn0[(size_t)MT*ATW];        // exp(scores), pad cols 0
__device__ __align__(256) __half g_attn1[(size_t)MT*ATW];
__device__ __align__(256) __half g_zcat[(size_t)MT*2*Cc];        // [b*NT+n][2C]
__device__ __align__(256) __half g_wh[655360];                   // fp16 weights
__device__ float g_psum[2*Bb*NT*NBLK];
__device__ float g_rowinv[2*Bb*NT];
__device__ float g_pre[3][(size_t)MT*Cc];
__device__ float g_fused[(size_t)Bb*Cc*NT];

__device__ __forceinline__ void cpa16(const void* smem_dst, const void* gsrc) {
    uint32_t s = (uint32_t)__cvta_generic_to_shared(smem_dst);
    asm volatile("cp.async.cg.shared.global [%0], [%1], 16;" :: "r"(s), "l"(gsrc));
}
__device__ __forceinline__ void ldsm_x4(unsigned* r, const __half* p) {
    uint32_t s = (uint32_t)__cvta_generic_to_shared(p);
    asm volatile("ldmatrix.sync.aligned.m8n8.x4.shared.b16 {%0,%1,%2,%3}, [%4];"
                 : "=r"(r[0]), "=r"(r[1]), "=r"(r[2]), "=r"(r[3]) : "r"(s));
}
__device__ __forceinline__ void ldsm_x4_t(unsigned* r, const __half* p) {
    uint32_t s = (uint32_t)__cvta_generic_to_shared(p);
    asm volatile("ldmatrix.sync.aligned.m8n8.x4.trans.shared.b16 {%0,%1,%2,%3}, [%4];"
                 : "=r"(r[0]), "=r"(r[1]), "=r"(r[2]), "=r"(r[3]) : "r"(s));
}

// ======== fp16 GEMM core: 64(M) x 128(N) block, 128 threads, warp tile 32x64 ========
// A: [m][k] halves (lda).
// BTRANS=0: B [n][k] (ldb). BTRANS=1: B [k][n] (ldb) via ldmatrix.trans.
template<int BTRANS>
__device__ __forceinline__ void gemm64_fp16(
    const __half* __restrict__ A, int lda,
    const __half* __restrict__ B, int ldb,
    int K, float acc[2][8][4])
{
    __shared__ __align__(16) __half As[2][64*SA];
    __shared__ __align__(16) __half Bs[2][BSW];
    const int tid = threadIdx.x, lane = tid & 31, warp = tid >> 5;
    const int wm = (warp >> 1) * 32, wn = (warp & 1) * 64;

    auto issue = [&](int k0, int bi) {
#pragma unroll
        for (int i = 0; i < 2; i++) {                 // A: 64 rows x 4 16B-chunks
            int idx = tid + i * 128;
            int row = idx >> 2, kg = (idx & 3) * 8;
            cpa16(&As[bi][row * SA + kg], A + (size_t)row * lda + k0 + kg);
        }
#pragma unroll
        for (int i = 0; i < 4; i++) {
            int idx = tid + i * 128;
            if (BTRANS) {                             // 32 k-rows x 16 chunks of n
                int row = idx >> 4, nc = (idx & 15) * 8;
                cpa16(&Bs[bi][row * SN + nc], B + (size_t)(k0 + row) * ldb + nc);
            } else {                                  // 128 n-rows x 4 chunks of k
                int row = idx >> 2, kg = (idx & 3) * 8;
                cpa16(&Bs[bi][row * SA + kg], B + (size_t)row * ldb + k0 + kg);
            }
        }
        asm volatile("cp.async.commit_group;");
    };

    issue(0, 0);
    int buf = 0;
    for (int k0 = 0; k0 < K; k0 += 32) {
        asm volatile("cp.async.wait_group 0;");
        __syncthreads();
        if (k0 + 32 < K) issue(k0 + 32, buf ^ 1);
        const __half* as = As[buf];
        const __half* bs = Bs[buf];
#pragma unroll
        for (int s = 0; s < 2; s++) {
            const int kk = s * 16;
            unsigned a[2][4], bf[4][4];
#pragma unroll
            for (int mi = 0; mi < 2; mi++)
                ldsm_x4(a[mi], &as[(wm + mi * 16 + (lane & 15)) * SA + kk + (lane >> 4) * 8]);
#pragma unroll
            for (int gi = 0; gi < 4; gi++) {
                if (BTRANS)
                    ldsm_x4_t(bf[gi], &bs[(kk + (lane & 7) + 8 * (lane >> 4)) * SN
                                          + wn + gi * 16 + 8 * ((lane >> 3) & 1)]);
                else
                    ldsm_x4(bf[gi], &bs[(wn + gi * 16 + (lane & 15)) * SA + kk + (lane >> 4) * 8]);
            }
#pragma unroll
            for (int mi = 0; mi < 2; mi++)
#pragma unroll
                for (int ni = 0; ni < 8; ni++) {
                    int gi = ni >> 1, hi = ni & 1;
                    asm volatile(
                        "mma.sync.aligned.m16n8k16.row.col.f32.f16.f16.f32 "
                        "{%0,%1,%2,%3}, {%4,%5,%6,%7}, {%8,%9}, {%0,%1,%2,%3};"
                        : "+f"(acc[mi][ni][0]), "+f"(acc[mi][ni][1]),
                          "+f"(acc[mi][ni][2]), "+f"(acc[mi][ni][3])
                        : "r"(a[mi][0]), "r"(a[mi][1]), "r"(a[mi][2]), "r"(a[mi][3]),
                          "r"(bf[gi][hi]), "r"(bf[gi][hi + 2]));
                }
        }
        buf ^= 1;
    }
}

// ---------------- weight prep: fp32 -> fp16 ----------------
__global__ void wprep_kernel(
    const float* w0, const float* w1, const float* w2, const float* w3,
    const float* w4, const float* w5, const float* w6, const float* w7, const float* w8)
{
    int seg = blockIdx.y;
    int idx = blockIdx.x * 256 + threadIdx.x;
    int size = (seg == 8) ? 131072 : 65536;
    if (idx >= size) return;
    const float* src;
    switch (seg) {
        case 0: src = w0; break; case 1: src = w1; break; case 2: src = w2; break;
        case 3: src = w3; break; case 4: src = w4; break; case 5: src = w5; break;
        case 6: src = w6; break; case 7: src = w7; break; default: src = w8; break;
    }
    g_wh[seg * 65536 + idx] = __float2half_rn(src[idx]);
}

// ---------------- downsample: 2x2 mean -> token-major fp16 [b][n][c] ----------------
__global__ void ds_kernel(const float* __restrict__ zr, const float* __restrict__ zi) {
    __shared__ float t[32][33];
    int b = blockIdx.z, n0 = blockIdx.x * 32, c0 = blockIdx.y * 32;
    int tx = threadIdx.x, ty = threadIdx.y;
#pragma unroll
    for (int m = 0; m < 2; m++) {
        const float* src = m ? zi : zr;
        __half* dst = m ? g_ds_ir : g_ds_rgb;
        if (m) __syncthreads();
#pragma unroll
        for (int i = 0; i < 4; i++) {
            int n = n0 + tx, c = c0 + ty + 8 * i;
            int ho = n / WDs, wo = n % WDs;
            const float* p = src + ((size_t)(b * Cc + c) * HH + 4 * ho + 1) * WW + 4 * wo + 1;
            t[tx][ty + 8 * i] = 0.25f * (p[0] + p[1] + p[WW] + p[WW + 1]);
        }
        __syncthreads();
#pragma unroll
        for (int i = 0; i < 4; i++) {
            int n = n0 + ty + 8 * i, c = c0 + tx;
            dst[((size_t)b * NT + n) * Cc + c] = __float2half_rn(t[ty + 8 * i][tx]);
        }
    }
}

// ---------------- projections: out = ds @ W^T + bias ----------------
__global__ void __launch_bounds__(128) proj_gemm(
    const float* __restrict__ bq_rgb, const float* __restrict__ bk_ir,
    const float* __restrict__ bv_ir,  const float* __restrict__ bq_ir,
    const float* __restrict__ bk_rgb, const float* __restrict__ bv_rgb)
{
    int b = blockIdx.x / 25, mloc = (blockIdx.x % 25) * 64;
    int n0 = blockIdx.y * 128, p = blockIdx.z;
    const __half* Ain = (p == 0 || p == 4 || p == 5) ? g_ds_rgb : g_ds_ir;
    const float* bias;
    switch (p) {
        case 0: bias = bq_rgb; break; case 1: bias = bk_ir;  break;
        case 2: bias = bv_ir;  break; case 3: bias = bq_ir;  break;
        case 4: bias = bk_rgb; break; default: bias = bv_rgb; break;
    }
    const __half* A = Ain + ((size_t)b * NT + mloc) * Cc;
    const __half* W = g_wh + p * 65536 + (size_t)n0 * Cc;
    float acc[2][8][4] = {};
    gemm64_fp16<0>(A, Cc, W, Cc, Cc, acc);

    const int tid = threadIdx.x, lane = tid & 31, warp = tid >> 5;
    const int wm = (warp >> 1) * 32, wn = (warp & 1) * 64;
    const int g = lane >> 2, tg = lane & 3;
    __half* out = g_tok[p] + ((size_t)b * NT + mloc) * Cc + n0;
#pragma unroll
    for (int mi = 0; mi < 2; mi++) {
        int r0 = wm + mi * 16 + g;
#pragma unroll
        for (int ni = 0; ni < 8; ni++) {
            int col = wn + ni * 8 + 2 * tg;
            float b0 = bias[n0 + col], b1 = bias[n0 + col + 1];
            *(__half2*)(out + (size_t)r0 * Cc + col) =
                __floats2half2_rn(acc[mi][ni][0] + b0, acc[mi][ni][1] + b1);
            *(__half2*)(out + (size_t)(r0 + 8) * Cc + col) =
                __floats2half2_rn(acc[mi][ni][2] + b0, acc[mi][ni][3] + b1);
        }
    }
}

// ---------------- scores: attn = exp((Q K^T)/16) fp16, partial rowsums ----------------
__global__ void __launch_bounds__(128) scores_gemm() {
    __shared__ float rsum[64];
    int m0 = blockIdx.x * 64, n0 = blockIdx.y * 128;
    int z = blockIdx.z, dir = z >> 3, b = z & 7;
    const __half* Aq = g_tok[dir ? 3 : 0] + ((size_t)b * NT + m0) * Cc;
    const __half* Bk = g_tok[dir ? 4 : 1] + ((size_t)b * NT + n0) * Cc;
    __half* out = (dir ? g_attn1 : g_attn0) + ((size_t)b * NT + m0) * ATW + n0;

    if (threadIdx.x < 64) rsum[threadIdx.x] = 0.f;
    float acc[2][8][4] = {};
    gemm64_fp16<0>(Aq, Cc, Bk, Cc, Cc, acc);

    const int tid = threadIdx.x, lane = tid & 31, warp = tid >> 5;
    const int wm = (warp >> 1) * 32, wn = (warp & 1) * 64;
    const int g = lane >> 2, tg = lane & 3;
#pragma unroll
    for (int mi = 0; mi < 2; mi++) {
        int r0 = wm + mi * 16 + g;
        float p0 = 0.f, p1 = 0.f;
#pragma unroll
        for (int ni = 0; ni < 8; ni++) {
            int col = wn + ni * 8 + 2 * tg;
            bool real = (n0 + col) < NT;
            float e0 = real ? __expf(acc[mi][ni][0] * 0.0625f) : 0.f;
            float e1 = real ? __expf(acc[mi][ni][1] * 0.0625f) : 0.f;
            float e2 = real ? __expf(acc[mi][ni][2] * 0.0625f) : 0.f;
            float e3 = real ? __expf(acc[mi][ni][3] * 0.0625f) : 0.f;
            *(__half2*)(out + (size_t)r0 * ATW + col) = __floats2half2_rn(e0, e1);
            *(__half2*)(out + (size_t)(r0 + 8) * ATW + col) = __floats2half2_rn(e2, e3);
            p0 += e0 + e1;
            p1 += e2 + e3;
        }
        p0 += __shfl_xor_sync(0xffffffffu, p0, 1); p0 += __shfl_xor_sync(0xffffffffu, p0, 2);
        p1 += __shfl_xor_sync(0xffffffffu, p1, 1); p1 += __shfl_xor_sync(0xffffffffu, p1, 2);
        if (tg == 0) {
            atomicAdd(&rsum[r0], p0);
            atomicAdd(&rsum[r0 + 8], p1);
        }
    }
    __syncthreads();
    if (tid < 64)
        g_psum[((size_t)z * NT + m0 + tid) * NBLK + blockIdx.y] = rsum[tid];
}

// ---------------- rowsum reduce ----------------
__global__ void rowinv_kernel() {
    int idx = blockIdx.x * blockDim.x + threadIdx.x;
    if (idx >= 2 * Bb * NT) return;
    float s = 0.f;
    const float* p = g_psum + (size_t)idx * NBLK;
#pragma unroll
    for (int j = 0; j < NBLK; j++) s += p[j];
    g_rowinv[idx] = 1.0f / s;
}

// ---------------- attn @ V (V consumed [k][n] via ldmatrix.trans) -> zcat ----------------
__global__ void __launch_bounds__(128) av_gemm() {
    int m0 = blockIdx.x * 64, n0 = blockIdx.y * 128;
    int z = blockIdx.z, dir = z >> 3, b = z & 7;
    const __half* P = (dir ? g_attn1 : g_attn0) + ((size_t)b * NT + m0) * ATW;
    const __half* V = g_tok[dir ? 5 : 2] + (size_t)b * NT * Cc + n0;   // [k][n], ldb=Cc
    float acc[2][8][4] = {};
    gemm64_fp16<1>(P, ATW, V, Cc, ATW, acc);

    const int tid = threadIdx.x, lane = tid & 31, warp = tid >> 5;
    const int wm = (warp >> 1) * 32, wn = (warp & 1) * 64;
    const int g = lane >> 2, tg = lane & 3;
    __half* out = g_zcat + ((size_t)b * NT + m0) * 2 * Cc + dir * Cc + n0;
    const float* rinv = g_rowinv + (size_t)z * NT + m0;
#pragma unroll
    for (int mi = 0; mi < 2; mi++) {
        int r0 = wm + mi * 16 + g;
        float i0 = rinv[r0], i1 = rinv[r0 + 8];
#pragma unroll
        for (int ni = 0; ni < 8; ni++) {
            int col = wn + ni * 8 + 2 * tg;
            *(__half2*)(out + (size_t)r0 * 2 * Cc + col) =
                __floats2half2_rn(acc[mi][ni][0] * i0, acc[mi][ni][1] * i0);
            *(__half2*)(out + (size_t)(r0 + 8) * 2 * Cc + col) =
                __floats2half2_rn(acc[mi][ni][2] * i1, acc[mi][ni][3] * i1);
        }
    }
}

// ---------------- epilogue GEMMs -> fp32 pre-activations ----------------
__global__ void __launch_bounds__(128) final_gemm(
    const float* __restrict__ brgb, const float* __restrict__ bir, const float* __restrict__ bz)
{
    int m0 = blockIdx.x * 64, n0 = blockIdx.y * 128, jj = blockIdx.z;
    const __half* A = g_zcat + (size_t)m0 * 2 * Cc + (jj == 1 ? Cc : 0);
    int Kd = (jj == 2) ? 2 * Cc : Cc;
    const __half* W    = (jj == 2) ? (g_wh + 524288) : (g_wh + (6 + jj) * 65536);
    const float* bias = (jj == 0) ? brgb : ((jj == 1) ? bir : bz);
    float acc[2][8][4] = {};
    gemm64_fp16<0>(A, 2 * Cc, W + (size_t)n0 * Kd, Kd, Kd, acc);

    const int tid = threadIdx.x, lane = tid & 31, warp = tid >> 5;
    const int wm = (warp >> 1) * 32, wn = (warp & 1) * 64;
    const int g = lane >> 2, tg = lane & 3;
    float* out = g_pre[jj] + (size_t)m0 * Cc + n0;
#pragma unroll
    for (int mi = 0; mi < 2; mi++) {
        int r0 = wm + mi * 16 + g;
#pragma unroll
        for (int ni = 0; ni < 8; ni++) {
            int col = wn + ni * 8 + 2 * tg;
            float b0 = bias[n0 + col], b1 = bias[n0 + col + 1];
            float2 v0 = { acc[mi][ni][0] + b0, acc[mi][ni][1] + b1 };
            float2 v1 = { acc[mi][ni][2] + b0, acc[mi][ni][3] + b1 };
            *(float2*)(out + (size_t)r0 * Cc + col) = v0;
            *(float2*)(out + (size_t)(r0 + 8) * Cc + col) = v1;
        }
    }
}

// ---------------- gate fuse + smem transpose to [B,C,N] ----------------
__global__ void fuse_kernel(const int* __restrict__ time_idx, const float* __restrict__ temb) {
    __shared__ float t[32][33];
    int b = blockIdx.z;
    int n0 = blockIdx.x * 32, c0 = blockIdx.y * 32;
    int tx = threadIdx.x, ty = threadIdx.y;
    int ti = time_idx[b];
#pragma unroll
    for (int i = 0; i < 4; i++) {
        int n = n0 + ty + 8 * i, c = c0 + tx;
        size_t m = ((size_t)b * NT + n) * Cc + c;
        float hr = tanhf(g_pre[0][m]);
        float hi = tanhf(g_pre[1][m]);
        float zb = 1.0f / (1.0f + __expf(-g_pre[2][m]));
        float te = temb[ti * Cc + c];
        float zf = 1.0f / (1.0f + __expf(-(zb + te)));
        t[ty + 8 * i][tx] = zf * hr + (1.0f - zf) * hi;
    }
    __syncthreads();
#pragma unroll
    for (int i = 0; i < 4; i++) {
        int c = c0 + ty + 8 * i, n = n0 + tx;
        g_fused[((size_t)b * Cc + c) * NT + n] = t[tx][ty + 8 * i];
    }
}

// ---------------- bilinear upsample 40 -> 160 ----------------
__global__ void upsample_kernel(float* __restrict__ out) {
    int idx = blockIdx.x * blockDim.x + threadIdx.x;
    if (idx >= Bb*Cc*HH*WW) return;
    int w  = idx % WW;
    int h  = (idx / WW) % HH;
    int bc = idx / (HH * WW);
    float sh = fmaxf(h * 0.25f - 0.375f, 0.0f);
    float sw = fmaxf(w * 0.25f - 0.375f, 0.0f);
    int h0 = (int)sh; float fh = sh - (float)h0; int h1 = min(h0 + 1, HDs - 1);
    int w0 = (int)sw; float fw = sw - (float)w0; int w1 = min(w0 + 1, WDs - 1);
    const float* p = g_fused + (size_t)bc * NT;
    float v00 = p[h0 * WDs + w0], v01 = p[h0 * WDs + w1];
    float v10 = p[h1 * WDs + w0], v11 = p[h1 * WDs + w1];
    float top = v00 * (1.0f - fw) + v01 * fw;
    float bot = v10 * (1.0f - fw) + v11 * fw;
    out[idx] = top * (1.0f - fh) + bot * fh;
}

extern "C" void kernel_launch(void* const* d_in, const int* in_sizes, int n_in,
                              void* d_out, int out_size) {
    const float* z_rgb  = (const float*)d_in[0];
    const float* z_ir   = (const float*)d_in[1];
    const int*   tidx   = (const int*)  d_in[2];
    const float* Wq_rgb = (const float*)d_in[3],  *bq_rgb = (const float*)d_in[4];
    const float* Wk_ir  = (const float*)d_in[5],  *bk_ir  = (const float*)d_in[6];
    const float* Wv_ir  = (const float*)d_in[7],  *bv_ir  = (const float*)d_in[8];
    const float* Wq_ir  = (const float*)d_in[9],  *bq_ir  = (const float*)d_in[10];
    const float* Wk_rgb = (const float*)d_in[11], *bk_rgb = (const float*)d_in[12];
    const float* Wv_rgb = (const float*)d_in[13], *bv_rgb = (const float*)d_in[14];
    const float* Wrgb   = (const float*)d_in[15], *brgb   = (const float*)d_in[16];
    const float* Wir    = (const float*)d_in[17], *bir    = (const float*)d_in[18];
    const float* Wz     = (const float*)d_in[19], *bz     = (const float*)d_in[20];
    const float* temb   = (const float*)d_in[21];

    wprep_kernel<<<dim3(512, 9), 256>>>(Wq_rgb, Wk_ir, Wv_ir, Wq_ir, Wk_rgb, Wv_rgb,
                                        Wrgb, Wir, Wz);
    ds_kernel<<<dim3(50, 8, 8), dim3(32, 8)>>>(z_rgb, z_ir);
    proj_gemm<<<dim3(200, 2, 6), 128>>>(bq_rgb, bk_ir, bv_ir, bq_ir, bk_rgb, bv_rgb);
    scores_gemm<<<dim3(25, NBLK, 16), 128>>>();
    rowinv_kernel<<<(2*Bb*NT + 255) / 256, 256>>>();
    av_gemm<<<dim3(25, 2, 16), 128>>>();
    final_gemm<<<dim3(200, 2, 3), 128>>>(brgb, bir, bz);
    fuse_kernel<<<dim3(NT/32, Cc/32, Bb), dim3(32, 8)>>>(tidx, temb);
    upsample_kernel<<<(Bb*Cc*HH*WW + 255) / 256, 256>>>((float*)d_out);
}

// round 10
// speedup vs baseline: 1.3532x; 1.0409x over previous
#include <cuda_runtime.h>
#include <cuda_fp16.h>
#include <math.h>
#include <float.h>
#include <stdint.h>

#define Bb  8
#define Cc  256
#define HH  160
#define WW  160
#define HDs 40
#define WDs 40
#define NT  1600
#define MT  (Bb*NT)
#define ATW 1664            // padded attention width (13*128)
#define NBLK 13
#define SA  40              // smem row stride (halves) for [r][k] tiles
#define SN  136             // smem row stride (halves) for [k][n] tiles (128+8)
#define ASW (64*SA)         // A smem halves per stage (2560)
#define BSW 5120            // B smem halves per stage: max(128*40, 32*136)

// ---------------- static scratch ----------------
__device__ __align__(256) __half g_ds_rgb[(size_t)Bb*NT*Cc];     // token-major [b][n][c]
__device__ __align__(256) __half g_ds_ir [(size_t)Bb*NT*Cc];
__device__ __align__(256) __half g_tok[6][(size_t)(MT+64)*Cc];   // [b*NT+n][c] (+zero tail)
__device__ __align__(256) __half g_attn0[(size_t)MT*ATW];        // exp(scores), pad cols 0
__device__ __align__(256) __half g_attn1[(size_t)MT*ATW];
__device__ __align__(256) __half g_zcat[(size_t)MT*2*Cc];        // [b*NT+n][2C]
__device__ __align__(256) __half g_wh[655360];                   // fp16 weights
__device__ float g_psum[2*Bb*NT*NBLK];
__device__ float g_rowinv[2*Bb*NT];
__device__ float g_pre[3][(size_t)MT*Cc];
__device__ float g_fused[(size_t)Bb*Cc*NT];

__device__ __forceinline__ void cpa16u(uint32_t smem_dst, const void* gsrc) {
    asm volatile("cp.async.cg.shared.global [%0], [%1], 16;" :: "r"(smem_dst), "l"(gsrc));
}
__device__ __forceinline__ void ldsm_x4u(unsigned* r, uint32_t s) {
    asm volatile("ldmatrix.sync.aligned.m8n8.x4.shared.b16 {%0,%1,%2,%3}, [%4];"
                 : "=r"(r[0]), "=r"(r[1]), "=r"(r[2]), "=r"(r[3]) : "r"(s));
}
__device__ __forceinline__ void ldsm_x4tu(unsigned* r, uint32_t s) {
    asm volatile("ldmatrix.sync.aligned.m8n8.x4.trans.shared.b16 {%0,%1,%2,%3}, [%4];"
                 : "=r"(r[0]), "=r"(r[1]), "=r"(r[2]), "=r"(r[3]) : "r"(s));
}

// ======== fp16 GEMM core: 64(M) x 128(N) block, 128 threads, 3-stage pipeline ========
// A: [m][k] halves (lda). BTRANS=0: B [n][k] (ldb). BTRANS=1: B [k][n] (ldb).
template<int BTRANS>
__device__ __forceinline__ void gemm64_fp16(
    const __half* __restrict__ A, int lda,
    const __half* __restrict__ B, int ldb,
    int K, float acc[2][8][4])
{
    __shared__ __align__(16) __half As[3][ASW];
    __shared__ __align__(16) __half Bs[3][BSW];
    const int tid = threadIdx.x, lane = tid & 31, warp = tid >> 5;
    const int wm = (warp >> 1) * 32, wn = (warp & 1) * 64;

    // ---- hoisted cp.async source/dest geometry ----
    const int a_row = tid >> 2, a_kg = (tid & 3) * 8;               // A: rows 0..31 (+32)
    const int bn_row = tid >> 2, bn_kg = (tid & 3) * 8;             // B[n][k]
    const int bt_row = tid >> 4, bt_nc = (tid & 15) * 8;            // B[k][n]
    const uint32_t as_b = (uint32_t)__cvta_generic_to_shared(&As[0][0]);
    const uint32_t bs_b = (uint32_t)__cvta_generic_to_shared(&Bs[0][0]);
    const uint32_t a_d0 = as_b + 2 * (a_row * SA + a_kg);
    const uint32_t a_d1 = a_d0 + 2 * (32 * SA);
    uint32_t b_d0, b_d1, b_d2, b_d3;
    if (BTRANS) {
        b_d0 = bs_b + 2 * (bt_row * SN + bt_nc);
        b_d1 = b_d0 + 2 * (8 * SN);
        b_d2 = b_d0 + 2 * (16 * SN);
        b_d3 = b_d0 + 2 * (24 * SN);
    } else {
        b_d0 = bs_b + 2 * (bn_row * SA + bn_kg);
        b_d1 = b_d0 + 2 * (32 * SA);
        b_d2 = b_d0 + 2 * (64 * SA);
        b_d3 = b_d0 + 2 * (96 * SA);
    }

    auto issue = [&](int ci) {
        int k0 = ci * 32;
        uint32_t ao = (ci % 3) * (ASW * 2), bo = (ci % 3) * (BSW * 2);
        cpa16u(a_d0 + ao, A + (size_t)a_row * lda + k0 + a_kg);
        cpa16u(a_d1 + ao, A + (size_t)(a_row + 32) * lda + k0 + a_kg);
        if (BTRANS) {
            const __half* gb = B + (size_t)(k0 + bt_row) * ldb + bt_nc;
            cpa16u(b_d0 + bo, gb);
            cpa16u(b_d1 + bo, gb + (size_t)8 * ldb);
            cpa16u(b_d2 + bo, gb + (size_t)16 * ldb);
            cpa16u(b_d3 + bo, gb + (size_t)24 * ldb);
        } else {
            const __half* gb = B + (size_t)bn_row * ldb + k0 + bn_kg;
            cpa16u(b_d0 + bo, gb);
            cpa16u(b_d1 + bo, gb + (size_t)32 * ldb);
            cpa16u(b_d2 + bo, gb + (size_t)64 * ldb);
            cpa16u(b_d3 + bo, gb + (size_t)96 * ldb);
        }
        asm volatile("cp.async.commit_group;");
    };

    // ---- hoisted ldmatrix addresses (per stage 0; add stage offset in loop) ----
    const uint32_t a_f0 = as_b + 2 * ((wm + (lane & 15)) * SA + (lane >> 4) * 8);
    const uint32_t a_f1 = a_f0 + 2 * (16 * SA);
    uint32_t b_f[4];
    if (BTRANS) {
        uint32_t base = bs_b + 2 * (((lane & 7) + 8 * (lane >> 4)) * SN
                                    + wn + 8 * ((lane >> 3) & 1));
#pragma unroll
        for (int gi = 0; gi < 4; gi++) b_f[gi] = base + 2 * (gi * 16);
    } else {
        uint32_t base = bs_b + 2 * ((wn + (lane & 15)) * SA + (lane >> 4) * 8);
#pragma unroll
        for (int gi = 0; gi < 4; gi++) b_f[gi] = base + 2 * (gi * 16 * SA);
    }

    const int nk = K / 32;
    issue(0);
    if (nk > 1) issue(1);
    for (int i = 0; i < nk; i++) {
        if (i + 1 < nk) asm volatile("cp.async.wait_group 1;");
        else            asm volatile("cp.async.wait_group 0;");
        __syncthreads();
        if (i + 2 < nk) issue(i + 2);
        const uint32_t ao = (i % 3) * (ASW * 2), bo = (i % 3) * (BSW * 2);
#pragma unroll
        for (int s = 0; s < 2; s++) {
            const int kk = s * 16;
            unsigned a[2][4], bf[4][4];
            ldsm_x4u(a[0], a_f0 + ao + 2 * kk);
            ldsm_x4u(a[1], a_f1 + ao + 2 * kk);
#pragma unroll
            for (int gi = 0; gi < 4; gi++) {
                if (BTRANS) ldsm_x4tu(bf[gi], b_f[gi] + bo + 2 * (kk * SN));
                else        ldsm_x4u (bf[gi], b_f[gi] + bo + 2 * kk);
            }
#pragma unroll
            for (int mi = 0; mi < 2; mi++)
#pragma unroll
                for (int ni = 0; ni < 8; ni++) {
                    int gi = ni >> 1, hi = ni & 1;
                    asm volatile(
                        "mma.sync.aligned.m16n8k16.row.col.f32.f16.f16.f32 "
                        "{%0,%1,%2,%3}, {%4,%5,%6,%7}, {%8,%9}, {%0,%1,%2,%3};"
                        : "+f"(acc[mi][ni][0]), "+f"(acc[mi][ni][1]),
                          "+f"(acc[mi][ni][2]), "+f"(acc[mi][ni][3])
                        : "r"(a[mi][0]), "r"(a[mi][1]), "r"(a[mi][2]), "r"(a[mi][3]),
                          "r"(bf[gi][hi]), "r"(bf[gi][hi + 2]));
                }
        }
    }
}

// ---------------- weight prep: fp32 -> fp16 ----------------
__global__ void wprep_kernel(
    const float* w0, const float* w1, const float* w2, const float* w3,
    const float* w4, const float* w5, const float* w6, const float* w7, const float* w8)
{
    int seg = blockIdx.y;
    int idx = blockIdx.x * 256 + threadIdx.x;
    int size = (seg == 8) ? 131072 : 65536;
    if (idx >= size) return;
    const float* src;
    switch (seg) {
        case 0: src = w0; break; case 1: src = w1; break; case 2: src = w2; break;
        case 3: src = w3; break; case 4: src = w4; break; case 5: src = w5; break;
        case 6: src = w6; break; case 7: src = w7; break; default: src = w8; break;
    }
    g_wh[seg * 65536 + idx] = __float2half_rn(src[idx]);
}

// ---------------- downsample: 2x2 mean -> token-major fp16 [b][n][c] ----------------
__global__ void ds_kernel(const float* __restrict__ zr, const float* __restrict__ zi) {
    __shared__ float t[32][33];
    int b = blockIdx.z, n0 = blockIdx.x * 32, c0 = blockIdx.y * 32;
    int tx = threadIdx.x, ty = threadIdx.y;
#pragma unroll
    for (int m = 0; m < 2; m++) {
        const float* src = m ? zi : zr;
        __half* dst = m ? g_ds_ir : g_ds_rgb;
        if (m) __syncthreads();
#pragma unroll
        for (int i = 0; i < 4; i++) {
            int n = n0 + tx, c = c0 + ty + 8 * i;
            int ho = n / WDs, wo = n % WDs;
            const float* p = src + ((size_t)(b * Cc + c) * HH + 4 * ho + 1) * WW + 4 * wo + 1;
            t[tx][ty + 8 * i] = 0.25f * (p[0] + p[1] + p[WW] + p[WW + 1]);
        }
        __syncthreads();
#pragma unroll
        for (int i = 0; i < 4; i++) {
            int n = n0 + ty + 8 * i, c = c0 + tx;
            dst[((size_t)b * NT + n) * Cc + c] = __float2half_rn(t[ty + 8 * i][tx]);
        }
    }
}

// ---------------- projections: out = ds @ W^T + bias ----------------
__global__ void __launch_bounds__(128) proj_gemm(
    const float* __restrict__ bq_rgb, const float* __restrict__ bk_ir,
    const float* __restrict__ bv_ir,  const float* __restrict__ bq_ir,
    const float* __restrict__ bk_rgb, const float* __restrict__ bv_rgb)
{
    int b = blockIdx.x / 25, mloc = (blockIdx.x % 25) * 64;
    int n0 = blockIdx.y * 128, p = blockIdx.z;
    const __half* Ain = (p == 0 || p == 4 || p == 5) ? g_ds_rgb : g_ds_ir;
    const float* bias;
    switch (p) {
        case 0: bias = bq_rgb; break; case 1: bias = bk_ir;  break;
        case 2: bias = bv_ir;  break; case 3: bias = bq_ir;  break;
        case 4: bias = bk_rgb; break; default: bias = bv_rgb; break;
    }
    const __half* A = Ain + ((size_t)b * NT + mloc) * Cc;
    const __half* W = g_wh + p * 65536 + (size_t)n0 * Cc;
    float acc[2][8][4] = {};
    gemm64_fp16<0>(A, Cc, W, Cc, Cc, acc);

    const int tid = threadIdx.x, lane = tid & 31, warp = tid >> 5;
    const int wm = (warp >> 1) * 32, wn = (warp & 1) * 64;
    const int g = lane >> 2, tg = lane & 3;
    __half* out = g_tok[p] + ((size_t)b * NT + mloc) * Cc + n0;
#pragma unroll
    for (int mi = 0; mi < 2; mi++) {
        int r0 = wm + mi * 16 + g;
#pragma unroll
        for (int ni = 0; ni < 8; ni++) {
            int col = wn + ni * 8 + 2 * tg;
            float b0 = bias[n0 + col], b1 = bias[n0 + col + 1];
            *(__half2*)(out + (size_t)r0 * Cc + col) =
                __floats2half2_rn(acc[mi][ni][0] + b0, acc[mi][ni][1] + b1);
            *(__half2*)(out + (size_t)(r0 + 8) * Cc + col) =
                __floats2half2_rn(acc[mi][ni][2] + b0, acc[mi][ni][3] + b1);
        }
    }
}

// ---------------- scores: attn = exp((Q K^T)/16) fp16, partial rowsums ----------------
__global__ void __launch_bounds__(128) scores_gemm() {
    __shared__ float rsum[64];
    int m0 = blockIdx.x * 64, n0 = blockIdx.y * 128;
    int z = blockIdx.z, dir = z >> 3, b = z & 7;
    const __half* Aq = g_tok[dir ? 3 : 0] + ((size_t)b * NT + m0) * Cc;
    const __half* Bk = g_tok[dir ? 4 : 1] + ((size_t)b * NT + n0) * Cc;
    __half* out = (dir ? g_attn1 : g_attn0) + ((size_t)b * NT + m0) * ATW + n0;

    if (threadIdx.x < 64) rsum[threadIdx.x] = 0.f;
    float acc[2][8][4] = {};
    gemm64_fp16<0>(Aq, Cc, Bk, Cc, Cc, acc);

    const int tid = threadIdx.x, lane = tid & 31, warp = tid >> 5;
    const int wm = (warp >> 1) * 32, wn = (warp & 1) * 64;
    const int g = lane >> 2, tg = lane & 3;
#pragma unroll
    for (int mi = 0; mi < 2; mi++) {
        int r0 = wm + mi * 16 + g;
        float p0 = 0.f, p1 = 0.f;
#pragma unroll
        for (int ni = 0; ni < 8; ni++) {
            int col = wn + ni * 8 + 2 * tg;
            bool real = (n0 + col) < NT;
            float e0 = real ? __expf(acc[mi][ni][0] * 0.0625f) : 0.f;
            float e1 = real ? __expf(acc[mi][ni][1] * 0.0625f) : 0.f;
            float e2 = real ? __expf(acc[mi][ni][2] * 0.0625f) : 0.f;
            float e3 = real ? __expf(acc[mi][ni][3] * 0.0625f) : 0.f;
            *(__half2*)(out + (size_t)r0 * ATW + col) = __floats2half2_rn(e0, e1);
            *(__half2*)(out + (size_t)(r0 + 8) * ATW + col) = __floats2half2_rn(e2, e3);
            p0 += e0 + e1;
            p1 += e2 + e3;
        }
        p0 += __shfl_xor_sync(0xffffffffu, p0, 1); p0 += __shfl_xor_sync(0xffffffffu, p0, 2);
        p1 += __shfl_xor_sync(0xffffffffu, p1, 1); p1 += __shfl_xor_sync(0xffffffffu, p1, 2);
        if (tg == 0) {
            atomicAdd(&rsum[r0], p0);
            atomicAdd(&rsum[r0 + 8], p1);
        }
    }
    __syncthreads();
    if (tid < 64)
        g_psum[((size_t)z * NT + m0 + tid) * NBLK + blockIdx.y] = rsum[tid];
}

// ---------------- rowsum reduce ----------------
__global__ void rowinv_kernel() {
    int idx = blockIdx.x * blockDim.x + threadIdx.x;
    if (idx >= 2 * Bb * NT) return;
    float s = 0.f;
    const float* p = g_psum + (size_t)idx * NBLK;
#pragma unroll
    for (int j = 0; j < NBLK; j++) s += p[j];
    g_rowinv[idx] = 1.0f / s;
}

// ---------------- attn @ V (V [k][n] via ldmatrix.trans) -> zcat ----------------
__global__ void __launch_bounds__(128) av_gemm() {
    int m0 = blockIdx.x * 64, n0 = blockIdx.y * 128;
    int z = blockIdx.z, dir = z >> 3, b = z & 7;
    const __half* P = (dir ? g_attn1 : g_attn0) + ((size_t)b * NT + m0) * ATW;
    const __half* V = g_tok[dir ? 5 : 2] + (size_t)b * NT * Cc + n0;   // [k][n], ldb=Cc
    float acc[2][8][4] = {};
    gemm64_fp16<1>(P, ATW, V, Cc, ATW, acc);

    const int tid = threadIdx.x, lane = tid & 31, warp = tid >> 5;
    const int wm = (warp >> 1) * 32, wn = (warp & 1) * 64;
    const int g = lane >> 2, tg = lane & 3;
    __half* out = g_zcat + ((size_t)b * NT + m0) * 2 * Cc + dir * Cc + n0;
    const float* rinv = g_rowinv + (size_t)z * NT + m0;
#pragma unroll
    for (int mi = 0; mi < 2; mi++) {
        int r0 = wm + mi * 16 + g;
        float i0 = rinv[r0], i1 = rinv[r0 + 8];
#pragma unroll
        for (int ni = 0; ni < 8; ni++) {
            int col = wn + ni * 8 + 2 * tg;
            *(__half2*)(out + (size_t)r0 * 2 * Cc + col) =
                __floats2half2_rn(acc[mi][ni][0] * i0, acc[mi][ni][1] * i0);
            *(__half2*)(out + (size_t)(r0 + 8) * 2 * Cc + col) =
                __floats2half2_rn(acc[mi][ni][2] * i1, acc[mi][ni][3] * i1);
        }
    }
}

// ---------------- epilogue GEMMs -> fp32 pre-activations ----------------
__global__ void __launch_bounds__(128) final_gemm(
    const float* __restrict__ brgb, const float* __restrict__ bir, const float* __restrict__ bz)
{
    int m0 = blockIdx.x * 64, n0 = blockIdx.y * 128, jj = blockIdx.z;
    const __half* A = g_zcat + (size_t)m0 * 2 * Cc + (jj == 1 ? Cc : 0);
    int Kd = (jj == 2) ? 2 * Cc : Cc;
    const __half* W    = (jj == 2) ? (g_wh + 524288) : (g_wh + (6 + jj) * 65536);
    const float* bias = (jj == 0) ? brgb : ((jj == 1) ? bir : bz);
    float acc[2][8][4] = {};
    gemm64_fp16<0>(A, 2 * Cc, W + (size_t)n0 * Kd, Kd, Kd, acc);

    const int tid = threadIdx.x, lane = tid & 31, warp = tid >> 5;
    const int wm = (warp >> 1) * 32, wn = (warp & 1) * 64;
    const int g = lane >> 2, tg = lane & 3;
    float* out = g_pre[jj] + (size_t)m0 * Cc + n0;
#pragma unroll
    for (int mi = 0; mi < 2; mi++) {
        int r0 = wm + mi * 16 + g;
#pragma unroll
        for (int ni = 0; ni < 8; ni++) {
            int col = wn + ni * 8 + 2 * tg;
            float b0 = bias[n0 + col], b1 = bias[n0 + col + 1];
            float2 v0 = { acc[mi][ni][0] + b0, acc[mi][ni][1] + b1 };
            float2 v1 = { acc[mi][ni][2] + b0, acc[mi][ni][3] + b1 };
            *(float2*)(out + (size_t)r0 * Cc + col) = v0;
            *(float2*)(out + (size_t)(r0 + 8) * Cc + col) = v1;
        }
    }
}

// ---------------- gate fuse + smem transpose to [B,C,N] ----------------
__global__ void fuse_kernel(const int* __restrict__ time_idx, const float* __restrict__ temb) {
    __shared__ float t[32][33];
    int b = blockIdx.z;
    int n0 = blockIdx.x * 32, c0 = blockIdx.y * 32;
    int tx = threadIdx.x, ty = threadIdx.y;
    int ti = time_idx[b];
#pragma unroll
    for (int i = 0; i < 4; i++) {
        int n = n0 + ty + 8 * i, c = c0 + tx;
        size_t m = ((size_t)b * NT + n) * Cc + c;
        float hr = tanhf(g_pre[0][m]);
        float hi = tanhf(g_pre[1][m]);
        float zb = 1.0f / (1.0f + __expf(-g_pre[2][m]));
        float te = temb[ti * Cc + c];
        float zf = 1.0f / (1.0f + __expf(-(zb + te)));
        t[ty + 8 * i][tx] = zf * hr + (1.0f - zf) * hi;
    }
    __syncthreads();
#pragma unroll
    for (int i = 0; i < 4; i++) {
        int c = c0 + ty + 8 * i, n = n0 + tx;
        g_fused[((size_t)b * Cc + c) * NT + n] = t[tx][ty + 8 * i];
    }
}

// ---------------- bilinear upsample 40 -> 160 ----------------
__global__ void upsample_kernel(float* __restrict__ out) {
    int idx = blockIdx.x * blockDim.x + threadIdx.x;
    if (idx >= Bb*Cc*HH*WW) return;
    int w  = idx % WW;
    int h  = (idx / WW) % HH;
    int bc = idx / (HH * WW);
    float sh = fmaxf(h * 0.25f - 0.375f, 0.0f);
    float sw = fmaxf(w * 0.25f - 0.375f, 0.0f);
    int h0 = (int)sh; float fh = sh - (float)h0; int h1 = min(h0 + 1, HDs - 1);
    int w0 = (int)sw; float fw = sw - (float)w0; int w1 = min(w0 + 1, WDs - 1);
    const float* p = g_fused + (size_t)bc * NT;
    float v00 = p[h0 * WDs + w0], v01 = p[h0 * WDs + w1];
    float v10 = p[h1 * WDs + w0], v11 = p[h1 * WDs + w1];
    float top = v00 * (1.0f - fw) + v01 * fw;
    float bot = v10 * (1.0f - fw) + v11 * fw;
    out[idx] = top * (1.0f - fh) + bot * fh;
}

extern "C" void kernel_launch(void* const* d_in, const int* in_sizes, int n_in,
                              void* d_out, int out_size) {
    const float* z_rgb  = (const float*)d_in[0];
    const float* z_ir   = (const float*)d_in[1];
    const int*   tidx   = (const int*)  d_in[2];
    const float* Wq_rgb = (const float*)d_in[3],  *bq_rgb = (const float*)d_in[4];
    const float* Wk_ir  = (const float*)d_in[5],  *bk_ir  = (const float*)d_in[6];
    const float* Wv_ir  = (const float*)d_in[7],  *bv_ir  = (const float*)d_in[8];
    const float* Wq_ir  = (const float*)d_in[9],  *bq_ir  = (const float*)d_in[10];
    const float* Wk_rgb = (const float*)d_in[11], *bk_rgb = (const float*)d_in[12];
    const float* Wv_rgb = (const float*)d_in[13], *bv_rgb = (const float*)d_in[14];
    const float* Wrgb   = (const float*)d_in[15], *brgb   = (const float*)d_in[16];
    const float* Wir    = (const float*)d_in[17], *bir    = (const float*)d_in[18];
    const float* Wz     = (const float*)d_in[19], *bz     = (const float*)d_in[20];
    const float* temb   = (const float*)d_in[21];

    wprep_kernel<<<dim3(512, 9), 256>>>(Wq_rgb, Wk_ir, Wv_ir, Wq_ir, Wk_rgb, Wv_rgb,
                                        Wrgb, Wir, Wz);
    ds_kernel<<<dim3(50, 8, 8), dim3(32, 8)>>>(z_rgb, z_ir);
    proj_gemm<<<dim3(200, 2, 6), 128>>>(bq_rgb, bk_ir, bv_ir, bq_ir, bk_rgb, bv_rgb);
    scores_gemm<<<dim3(25, NBLK, 16), 128>>>();
    rowinv_kernel<<<(2*Bb*NT + 255) / 256, 256>>>();
    av_gemm<<<dim3(25, 2, 16), 128>>>();
    final_gemm<<<dim3(200, 2, 3), 128>>>(brgb, bir, bz);
    fuse_kernel<<<dim3(NT/32, Cc/32, Bb), dim3(32, 8)>>>(tidx, temb);
    upsample_kernel<<<(Bb*Cc*HH*WW + 255) / 256, 256>>>((float*)d_out);
}